// round 12
// baseline (speedup 1.0000x reference)
#include <cuda_runtime.h>
#include <cuda_fp16.h>
#include <cstdint>

// LSTM cell: gates = [x|h] @ [Wx;Wh] + bx + bh, fused epilogue.
// B=16384, IN=H=512, K=1024, N=4H=2048.
// Round 12: issue-order fix -- every blocking point (producer burst,
// full-wait, ldmatrix) is preceded by a 32-MMA block so the tensor queue
// never drains while a warp stalls. Otherwise identical to R11.

static constexpr int Bsz  = 16384;
static constexpr int INF  = 512;
static constexpr int Hd   = 512;
static constexpr int FH   = 2048;
static constexpr int Ktot = 1024;

#define BM 128
#define BN 128
#define BK 64
#define NSTAGE 3
#define NITER (Ktot / BK)              // 16
#define ROWSTR 72                      // halves per SMEM row (144 B)
#define A_STG_B (BM * ROWSTR * 2)
#define B_STG_B (BN * ROWSTR * 2)
#define STG_B   (A_STG_B + B_STG_B)    // 36864 B
#define SMEM_BYTES (1024 + NSTAGE * STG_B)   // 111616

#define PREP_A_BLKS 4096
#define PREP_W_BLKS (32 * 64)
#define PREP_BLKS   (PREP_A_BLKS + PREP_W_BLKS)

__device__ __half g_A16[(size_t)Bsz * Ktot];
__device__ __half g_Bt16[(size_t)FH * Ktot];

// ---------------- helpers ----------------
__device__ __forceinline__ uint32_t cvta_s(const void* p) {
    return (uint32_t)__cvta_generic_to_shared(p);
}
__device__ __forceinline__ void cpa16(uint32_t s, const void* g) {
    asm volatile("cp.async.cg.shared.global [%0], [%1], 16;"
                 :: "r"(s), "l"(g) : "memory");
}
__device__ __forceinline__ void mbar_init(uint32_t a, uint32_t cnt) {
    asm volatile("mbarrier.init.shared.b64 [%0], %1;" :: "r"(a), "r"(cnt) : "memory");
}
__device__ __forceinline__ void mbar_arrive(uint32_t a) {
    asm volatile("mbarrier.arrive.shared.b64 _, [%0];" :: "r"(a) : "memory");
}
__device__ __forceinline__ void cpa_mbar_arrive(uint32_t a) {
    asm volatile("cp.async.mbarrier.arrive.noinc.shared.b64 [%0];"
                 :: "r"(a) : "memory");
}
__device__ __forceinline__ void mbar_wait(uint32_t a, uint32_t ph) {
    uint32_t done = 0;
    while (!done) {
        asm volatile(
            "{\n\t.reg .pred p;\n\t"
            "mbarrier.try_wait.parity.acquire.cta.shared::cta.b64 p, [%1], %2, 0x989680;\n\t"
            "selp.b32 %0, 1, 0, p;\n\t}"
            : "=r"(done) : "r"(a), "r"(ph) : "memory");
    }
}
__device__ __forceinline__ void ldm4(uint32_t* r, uint32_t a) {
    asm volatile("ldmatrix.sync.aligned.m8n8.x4.shared.b16 {%0,%1,%2,%3}, [%4];"
                 : "=r"(r[0]), "=r"(r[1]), "=r"(r[2]), "=r"(r[3]) : "r"(a));
}
__device__ __forceinline__ void mma16(float* d, const uint32_t* a, const uint32_t* b) {
    asm volatile(
        "mma.sync.aligned.m16n8k16.row.col.f32.f16.f16.f32 "
        "{%0,%1,%2,%3}, {%4,%5,%6,%7}, {%8,%9}, {%0,%1,%2,%3};"
        : "+f"(d[0]), "+f"(d[1]), "+f"(d[2]), "+f"(d[3])
        : "r"(a[0]), "r"(a[1]), "r"(a[2]), "r"(a[3]), "r"(b[0]), "r"(b[1]));
}
__device__ __forceinline__ float rcp_(float a) {
    float r; asm("rcp.approx.f32 %0, %1;" : "=f"(r) : "f"(a)); return r;
}
__device__ __forceinline__ float sigm_(float v) { return rcp_(1.0f + __expf(-v)); }
__device__ __forceinline__ float tanh_(float v) {
    return 2.0f * rcp_(1.0f + __expf(-2.0f * v)) - 1.0f;
}
__device__ __forceinline__ uint2 pack4h(float a, float b, float cc, float d) {
    union { __half2 h2[2]; uint2 u; } u;
    u.h2[0] = __floats2half2_rn(a, b);
    u.h2[1] = __floats2half2_rn(cc, d);
    return u.u;
}

// ---------------- merged prepass (unchanged, verified) ----------------
__global__ void prep_all(const float* __restrict__ x, const float* __restrict__ h,
                         const float* __restrict__ Wx, const float* __restrict__ Wh)
{
    if (blockIdx.x < PREP_A_BLKS) {
        const size_t t = (size_t)blockIdx.x * 256 + threadIdx.x;
        const size_t NQ = (size_t)Bsz * INF / 4;
        const size_t S  = NQ / 2;
        float4 vx0 = *reinterpret_cast<const float4*>(x + (t)     * 4);
        float4 vx1 = *reinterpret_cast<const float4*>(x + (t + S) * 4);
        float4 vh0 = *reinterpret_cast<const float4*>(h + (t)     * 4);
        float4 vh1 = *reinterpret_cast<const float4*>(h + (t + S) * 4);
        {   size_t b = t >> 7, c4 = (t & 127) * 4;
            *reinterpret_cast<uint2*>(g_A16 + b * Ktot + c4) =
                pack4h(vx0.x, vx0.y, vx0.z, vx0.w); }
        {   size_t q = t + S; size_t b = q >> 7, c4 = (q & 127) * 4;
            *reinterpret_cast<uint2*>(g_A16 + b * Ktot + c4) =
                pack4h(vx1.x, vx1.y, vx1.z, vx1.w); }
        {   size_t b = t >> 7, c4 = (t & 127) * 4;
            *reinterpret_cast<uint2*>(g_A16 + b * Ktot + 512 + c4) =
                pack4h(vh0.x, vh0.y, vh0.z, vh0.w); }
        {   size_t q = t + S; size_t b = q >> 7, c4 = (q & 127) * 4;
            *reinterpret_cast<uint2*>(g_A16 + b * Ktot + 512 + c4) =
                pack4h(vh1.x, vh1.y, vh1.z, vh1.w); }
        return;
    }

    __shared__ float t[32][33];
    const int wb = blockIdx.x - PREP_A_BLKS;
    const int k0 = (wb & 31) * 32;
    const int n0 = (wb >> 5) * 32;
    const float* W = (k0 < INF) ? (Wx + (size_t)k0 * FH)
                                : (Wh + (size_t)(k0 - INF) * FH);
    const int tx = threadIdx.x & 31, ty = threadIdx.x >> 5;
    #pragma unroll
    for (int i = 0; i < 4; ++i) {
        int kk = ty + i * 8;
        t[kk][tx] = W[(size_t)kk * FH + n0 + tx];
    }
    __syncthreads();
    const int gate = n0 >> 9;
    const int j0   = n0 & 511;
    #pragma unroll
    for (int i = 0; i < 4; ++i) {
        int nn = ty + i * 8;
        int j  = j0 + nn;
        int np = ((j >> 4) << 6) + gate * 16 + (j & 15);
        g_Bt16[(size_t)np * Ktot + k0 + tx] = __float2half_rn(t[tx][nn]);
    }
}

// ---------------- main GEMM + LSTM epilogue ----------------
__global__ __launch_bounds__(128, 2)
void lstm_mma(const float* __restrict__ c,
              const float* __restrict__ bx, const float* __restrict__ bh,
              float* __restrict__ out)
{
    extern __shared__ char smraw[];
    float* biasS = reinterpret_cast<float*>(smraw);
    char*  stg0  = smraw + 1024;

    const int tid  = threadIdx.x;
    const int lane = tid & 31;
    const int wid  = tid >> 5;
    const int wm   = wid >> 1;
    const int wn   = wid & 1;
    const int m0   = blockIdx.y * BM;
    const int n0   = blockIdx.x * BN;
    const int jb   = blockIdx.x * 32;

    const uint32_t sbase = cvta_s(smraw);
    const uint32_t FULLB = sbase + 512;
    const uint32_t EMPTB = sbase + 512 + 24;

    if (tid == 0) {
        #pragma unroll
        for (int s = 0; s < NSTAGE; ++s) {
            mbar_init(FULLB + s * 8, 128);
            mbar_init(EMPTB + s * 8, 128);
        }
    }
    {   int g = tid >> 5, jj = tid & 31;
        int colg = g * 512 + jb + jj;
        biasS[tid] = bx[colg] + bh[colg];
    }
    __syncthreads();

    float acc[4][8][4];
    #pragma unroll
    for (int a = 0; a < 4; ++a)
        #pragma unroll
        for (int b = 0; b < 8; ++b)
            #pragma unroll
            for (int d = 0; d < 4; ++d) acc[a][b][d] = 0.0f;

    const int grp = lane >> 3, gi = lane & 7;
    const int a_row  = wm * 64 + (grp & 1) * 8 + gi;
    const int a_kofs = (grp >> 1) * 8;
    const uint32_t a_base = (uint32_t)(a_row * ROWSTR + a_kofs) * 2;
    const int b_row  = wn * 64 + (grp >> 1) * 8 + gi;
    const int b_kofs = (grp & 1) * 8;
    const uint32_t b_base = (uint32_t)(b_row * ROWSTR + b_kofs) * 2;

    auto load_stage = [&](int s, int kc) {
        const int k0 = kc * BK;
        char* As = stg0 + s * STG_B;
        char* Bs = As + A_STG_B;
        const __half* Ap = g_A16 + (size_t)m0 * Ktot + k0;
        #pragma unroll
        for (int p = 0; p < 8; ++p) {
            int q = tid + 128 * p, row = q >> 3, c8 = (q & 7) * 8;
            cpa16(cvta_s(As + (row * ROWSTR + c8) * 2),
                  Ap + (size_t)row * Ktot + c8);
        }
        const __half* Bp = g_Bt16 + (size_t)n0 * Ktot + k0;
        #pragma unroll
        for (int p = 0; p < 8; ++p) {
            int q = tid + 128 * p, row = q >> 3, c8 = (q & 7) * 8;
            cpa16(cvta_s(Bs + (row * ROWSTR + c8) * 2),
                  Bp + (size_t)row * Ktot + c8);
        }
        cpa_mbar_arrive(FULLB + s * 8);
    };

    load_stage(0, 0);
    load_stage(1, 1);

    uint32_t afr[2][4][4], bfr[2][4][4];
    int fph0 = 0, fph1 = 0, fph2 = 0;
    int eph0 = 0, eph1 = 0, eph2 = 0;

    // prologue: wait stage 0, preload its ks=0 fragments into buf0
    mbar_wait(FULLB + 0, 0); fph0 = 1;
    {
        const uint32_t sA = cvta_s(stg0);
        const uint32_t sB = sA + A_STG_B;
        #pragma unroll
        for (int mf = 0; mf < 4; ++mf)
            ldm4(afr[0][mf], sA + a_base + mf * (16 * ROWSTR * 2));
        #pragma unroll
        for (int np = 0; np < 4; ++np)
            ldm4(bfr[0][np], sB + b_base + np * (16 * ROWSTR * 2));
    }

    // MMA block over one k16 step from buffer `buf`
    auto mma_block = [&](int buf) {
        #pragma unroll
        for (int mf = 0; mf < 4; ++mf)
            #pragma unroll
            for (int np = 0; np < 4; ++np) {
                mma16(acc[mf][np * 2 + 0], afr[buf][mf], &bfr[buf][np][0]);
                mma16(acc[mf][np * 2 + 1], afr[buf][mf], &bfr[buf][np][2]);
            }
    };
    // ldm block for k-step ko of the stage at (sA,sB) into buffer `buf`
    auto ldm_block = [&](int buf, uint32_t sA, uint32_t sB, int ko) {
        #pragma unroll
        for (int mf = 0; mf < 4; ++mf)
            ldm4(afr[buf][mf], sA + a_base + mf * (16 * ROWSTR * 2) + ko * 32);
        #pragma unroll
        for (int np = 0; np < 4; ++np)
            ldm4(bfr[buf][np], sB + b_base + np * (16 * ROWSTR * 2) + ko * 32);
    };

    for (int it = 0; it < NITER; ++it) {
        const int s = it % NSTAGE;
        const uint32_t sA = cvta_s(stg0 + s * STG_B);
        const uint32_t sB = sA + A_STG_B;

        // ks=0 MMAs first (frags preloaded at prev-iter end) -> tensor busy
        mma_block(0);

        // producer burst covered by ks0 MMAs in flight
        if (it + 2 < NITER) {
            const int s2 = (it + 2) % NSTAGE;
            if (it > 0) {
                int ph = (s2 == 0) ? eph0 : (s2 == 1) ? eph1 : eph2;
                mbar_wait(EMPTB + s2 * 8, ph);
                if (s2 == 0) eph0 ^= 1; else if (s2 == 1) eph1 ^= 1; else eph2 ^= 1;
            }
            load_stage(s2, it + 2);
        }

        ldm_block(1, sA, sB, 1);
        mma_block(1);                        // ks=1

        ldm_block(0, sA, sB, 2);
        mma_block(0);                        // ks=2

        ldm_block(1, sA, sB, 3);
        mbar_arrive(EMPTB + s * 8);          // last smem read of stage s issued
        mma_block(1);                        // ks=3

        // cross-stage prefetch AFTER ks3 MMAs: wait is covered by them
        if (it + 1 < NITER) {
            const int s1 = (it + 1) % NSTAGE;
            int ph = (s1 == 0) ? fph0 : (s1 == 1) ? fph1 : fph2;
            mbar_wait(FULLB + s1 * 8, ph);
            if (s1 == 0) fph0 ^= 1; else if (s1 == 1) fph1 ^= 1; else fph2 ^= 1;
            const uint32_t nA = cvta_s(stg0 + s1 * STG_B);
            const uint32_t nB = nA + A_STG_B;
            ldm_block(0, nA, nB, 0);
        }
    }

    // ---- fused LSTM epilogue (thread-local: all 4 gates per j) ----
    const size_t HC = (size_t)Bsz * Hd;
    #pragma unroll
    for (int mf = 0; mf < 4; ++mf) {
        #pragma unroll
        for (int e = 0; e < 2; ++e) {
            size_t row = (size_t)m0 + wm * 64 + mf * 16 + (lane >> 2) + e * 8;
            #pragma unroll
            for (int half = 0; half < 2; ++half) {
                int q  = 2 * (lane & 3) + half * 8;
                int bq = wn * 16 + q;
                int j  = jb + bq;
                float2 cold = *reinterpret_cast<const float2*>(c + row * 512 + j);
                float hv[2], cv[2];
                #pragma unroll
                for (int d = 0; d < 2; ++d) {
                    float gi = acc[mf][0 + half][e * 2 + d] + biasS[     bq + d];
                    float gf = acc[mf][2 + half][e * 2 + d] + biasS[32 + bq + d];
                    float gg = acc[mf][4 + half][e * 2 + d] + biasS[64 + bq + d];
                    float go = acc[mf][6 + half][e * 2 + d] + biasS[96 + bq + d];
                    float i_ = sigm_(gi), f_ = sigm_(gf);
                    float g_ = tanh_(gg), o_ = sigm_(go);
                    float co = d ? cold.y : cold.x;
                    float cn = f_ * co + i_ * g_;
                    cv[d] = cn;
                    hv[d] = o_ * tanh_(cn);
                }
                *reinterpret_cast<float2*>(out + row * 512 + j) =
                    make_float2(hv[0], hv[1]);
                *reinterpret_cast<float2*>(out + HC + row * 512 + j) =
                    make_float2(cv[0], cv[1]);
            }
        }
    }
}

extern "C" void kernel_launch(void* const* d_in, const int* in_sizes, int n_in,
                              void* d_out, int out_size) {
    const float* x  = (const float*)d_in[0];
    const float* h  = (const float*)d_in[1];
    const float* c  = (const float*)d_in[2];
    const float* Wx = (const float*)d_in[3];
    const float* Wh = (const float*)d_in[4];
    const float* bx = (const float*)d_in[5];
    const float* bh = (const float*)d_in[6];
    float* out = (float*)d_out;

    static bool attr_set = false;
    if (!attr_set) {
        cudaFuncSetAttribute(lstm_mma,
                             cudaFuncAttributeMaxDynamicSharedMemorySize,
                             SMEM_BYTES);
        attr_set = true;
    }

    prep_all<<<PREP_BLKS, 256>>>(x, h, Wx, Wh);
    lstm_mma<<<dim3(FH / BN, Bsz / BM), 128, SMEM_BYTES>>>(c, bx, bh, out);
}

// round 13
// speedup vs baseline: 1.0115x; 1.0115x over previous
#include <cuda_runtime.h>
#include <cuda_fp16.h>
#include <cstdint>

// LSTM cell: gates = [x|h] @ [Wx;Wh] + bx + bh, fused epilogue.
// B=16384, IN=H=512, K=1024, N=4H=2048.
// Round 13: mainloop reverted to R11 (best). prep_A rebuilt with 16B
// stores + MLP=8. L2 prefetch of the c tile at CTA start to de-cold the
// epilogue's c reads.

static constexpr int Bsz  = 16384;
static constexpr int INF  = 512;
static constexpr int Hd   = 512;
static constexpr int FH   = 2048;
static constexpr int Ktot = 1024;

#define BM 128
#define BN 128
#define BK 64
#define NSTAGE 3
#define NITER (Ktot / BK)              // 16
#define ROWSTR 72                      // halves per SMEM row (144 B)
#define A_STG_B (BM * ROWSTR * 2)
#define B_STG_B (BN * ROWSTR * 2)
#define STG_B   (A_STG_B + B_STG_B)    // 36864 B
#define SMEM_BYTES (1024 + NSTAGE * STG_B)   // 111616

#define PREP_A_BLKS 2048               // 2048 blk * 256 thr: 512K threads
#define PREP_W_BLKS (32 * 64)
#define PREP_BLKS   (PREP_A_BLKS + PREP_W_BLKS)

__device__ __half g_A16[(size_t)Bsz * Ktot];   // 32 MB  [b][k]  (x | h)
__device__ __half g_Bt16[(size_t)FH * Ktot];   // 4 MB   [n'][k] gate-interleaved(16)

// ---------------- helpers ----------------
__device__ __forceinline__ uint32_t cvta_s(const void* p) {
    return (uint32_t)__cvta_generic_to_shared(p);
}
__device__ __forceinline__ void cpa16(uint32_t s, const void* g) {
    asm volatile("cp.async.cg.shared.global [%0], [%1], 16;"
                 :: "r"(s), "l"(g) : "memory");
}
__device__ __forceinline__ void mbar_init(uint32_t a, uint32_t cnt) {
    asm volatile("mbarrier.init.shared.b64 [%0], %1;" :: "r"(a), "r"(cnt) : "memory");
}
__device__ __forceinline__ void mbar_arrive(uint32_t a) {
    asm volatile("mbarrier.arrive.shared.b64 _, [%0];" :: "r"(a) : "memory");
}
__device__ __forceinline__ void cpa_mbar_arrive(uint32_t a) {
    asm volatile("cp.async.mbarrier.arrive.noinc.shared.b64 [%0];"
                 :: "r"(a) : "memory");
}
__device__ __forceinline__ void mbar_wait(uint32_t a, uint32_t ph) {
    uint32_t done = 0;
    while (!done) {
        asm volatile(
            "{\n\t.reg .pred p;\n\t"
            "mbarrier.try_wait.parity.acquire.cta.shared::cta.b64 p, [%1], %2, 0x989680;\n\t"
            "selp.b32 %0, 1, 0, p;\n\t}"
            : "=r"(done) : "r"(a), "r"(ph) : "memory");
    }
}
__device__ __forceinline__ void ldm4(uint32_t* r, uint32_t a) {
    asm volatile("ldmatrix.sync.aligned.m8n8.x4.shared.b16 {%0,%1,%2,%3}, [%4];"
                 : "=r"(r[0]), "=r"(r[1]), "=r"(r[2]), "=r"(r[3]) : "r"(a));
}
__device__ __forceinline__ void mma16(float* d, const uint32_t* a, const uint32_t* b) {
    asm volatile(
        "mma.sync.aligned.m16n8k16.row.col.f32.f16.f16.f32 "
        "{%0,%1,%2,%3}, {%4,%5,%6,%7}, {%8,%9}, {%0,%1,%2,%3};"
        : "+f"(d[0]), "+f"(d[1]), "+f"(d[2]), "+f"(d[3])
        : "r"(a[0]), "r"(a[1]), "r"(a[2]), "r"(a[3]), "r"(b[0]), "r"(b[1]));
}
__device__ __forceinline__ float rcp_(float a) {
    float r; asm("rcp.approx.f32 %0, %1;" : "=f"(r) : "f"(a)); return r;
}
__device__ __forceinline__ float sigm_(float v) { return rcp_(1.0f + __expf(-v)); }
__device__ __forceinline__ float tanh_(float v) {
    return 2.0f * rcp_(1.0f + __expf(-2.0f * v)) - 1.0f;
}
__device__ __forceinline__ uint4 pack8h(const float4& a, const float4& b) {
    union { __half2 h2[4]; uint4 u; } u;
    u.h2[0] = __floats2half2_rn(a.x, a.y);
    u.h2[1] = __floats2half2_rn(a.z, a.w);
    u.h2[2] = __floats2half2_rn(b.x, b.y);
    u.h2[3] = __floats2half2_rn(b.z, b.w);
    return u.u;
}

// ---------------- merged prepass ----------------
// blocks [0, PREP_A_BLKS): x|h -> g_A16 fp16. Each thread: 2 groups of 8
// floats from x and 2 from h (8 independent LDG.128), 4 STG.128 stores.
// rest: 32x32 W transpose tiles -> g_Bt16 (gate-interleave 16).
__global__ void prep_all(const float* __restrict__ x, const float* __restrict__ h,
                         const float* __restrict__ Wx, const float* __restrict__ Wh)
{
    if (blockIdx.x < PREP_A_BLKS) {
        const size_t t = (size_t)blockIdx.x * 256 + threadIdx.x;   // 512K threads
        const size_t NG = (size_t)Bsz * INF / 8;                   // 1M groups/stream
        const size_t S  = NG / 2;                                  // 512K
        const size_t g0 = t, g1 = t + S;
        // 8 independent 16B loads
        float4 x0a = *reinterpret_cast<const float4*>(x + g0 * 8);
        float4 x0b = *reinterpret_cast<const float4*>(x + g0 * 8 + 4);
        float4 x1a = *reinterpret_cast<const float4*>(x + g1 * 8);
        float4 x1b = *reinterpret_cast<const float4*>(x + g1 * 8 + 4);
        float4 h0a = *reinterpret_cast<const float4*>(h + g0 * 8);
        float4 h0b = *reinterpret_cast<const float4*>(h + g0 * 8 + 4);
        float4 h1a = *reinterpret_cast<const float4*>(h + g1 * 8);
        float4 h1b = *reinterpret_cast<const float4*>(h + g1 * 8 + 4);
        {   size_t b = g0 >> 6, c8 = (g0 & 63) * 8;
            *reinterpret_cast<uint4*>(g_A16 + b * Ktot + c8) = pack8h(x0a, x0b);
            *reinterpret_cast<uint4*>(g_A16 + b * Ktot + 512 + c8) = pack8h(h0a, h0b);
        }
        {   size_t b = g1 >> 6, c8 = (g1 & 63) * 8;
            *reinterpret_cast<uint4*>(g_A16 + b * Ktot + c8) = pack8h(x1a, x1b);
            *reinterpret_cast<uint4*>(g_A16 + b * Ktot + 512 + c8) = pack8h(h1a, h1b);
        }
        return;
    }

    __shared__ float t[32][33];
    const int wb = blockIdx.x - PREP_A_BLKS;
    const int k0 = (wb & 31) * 32;
    const int n0 = (wb >> 5) * 32;
    const float* W = (k0 < INF) ? (Wx + (size_t)k0 * FH)
                                : (Wh + (size_t)(k0 - INF) * FH);
    const int tx = threadIdx.x & 31, ty = threadIdx.x >> 5;
    #pragma unroll
    for (int i = 0; i < 4; ++i) {
        int kk = ty + i * 8;
        t[kk][tx] = W[(size_t)kk * FH + n0 + tx];
    }
    __syncthreads();
    const int gate = n0 >> 9;
    const int j0   = n0 & 511;
    #pragma unroll
    for (int i = 0; i < 4; ++i) {
        int nn = ty + i * 8;
        int j  = j0 + nn;
        int np = ((j >> 4) << 6) + gate * 16 + (j & 15);
        g_Bt16[(size_t)np * Ktot + k0 + tx] = __float2half_rn(t[tx][nn]);
    }
}

// ---------------- main GEMM + LSTM epilogue (R11 mainloop) ----------------
__global__ __launch_bounds__(128, 2)
void lstm_mma(const float* __restrict__ c,
              const float* __restrict__ bx, const float* __restrict__ bh,
              float* __restrict__ out)
{
    extern __shared__ char smraw[];
    float* biasS = reinterpret_cast<float*>(smraw);
    char*  stg0  = smraw + 1024;

    const int tid  = threadIdx.x;
    const int lane = tid & 31;
    const int wid  = tid >> 5;
    const int wm   = wid >> 1;
    const int wn   = wid & 1;
    const int m0   = blockIdx.y * BM;
    const int n0   = blockIdx.x * BN;
    const int jb   = blockIdx.x * 32;

    const uint32_t sbase = cvta_s(smraw);
    const uint32_t FULLB = sbase + 512;
    const uint32_t EMPTB = sbase + 512 + 24;

    if (tid == 0) {
        #pragma unroll
        for (int s = 0; s < NSTAGE; ++s) {
            mbar_init(FULLB + s * 8, 128);
            mbar_init(EMPTB + s * 8, 128);
        }
    }
    {   int g = tid >> 5, jj = tid & 31;
        int colg = g * 512 + jb + jj;
        biasS[tid] = bx[colg] + bh[colg];
    }
    // Warm L2 with this CTA's c tile (epilogue reads it; zero reg cost).
    {   const float* cp = c + (size_t)(m0 + tid) * Hd + jb;   // 128B segment
        asm volatile("prefetch.global.L2 [%0];" :: "l"(cp));
    }
    __syncthreads();    // only CTA-wide barrier

    float acc[4][8][4];
    #pragma unroll
    for (int a = 0; a < 4; ++a)
        #pragma unroll
        for (int b = 0; b < 8; ++b)
            #pragma unroll
            for (int d = 0; d < 4; ++d) acc[a][b][d] = 0.0f;

    const int grp = lane >> 3, gi = lane & 7;
    const int a_row  = wm * 64 + (grp & 1) * 8 + gi;
    const int a_kofs = (grp >> 1) * 8;
    const uint32_t a_base = (uint32_t)(a_row * ROWSTR + a_kofs) * 2;
    const int b_row  = wn * 64 + (grp >> 1) * 8 + gi;
    const int b_kofs = (grp & 1) * 8;
    const uint32_t b_base = (uint32_t)(b_row * ROWSTR + b_kofs) * 2;

    auto load_stage = [&](int s, int kc) {
        const int k0 = kc * BK;
        char* As = stg0 + s * STG_B;
        char* Bs = As + A_STG_B;
        const __half* Ap = g_A16 + (size_t)m0 * Ktot + k0;
        #pragma unroll
        for (int p = 0; p < 8; ++p) {
            int q = tid + 128 * p, row = q >> 3, c8 = (q & 7) * 8;
            cpa16(cvta_s(As + (row * ROWSTR + c8) * 2),
                  Ap + (size_t)row * Ktot + c8);
        }
        const __half* Bp = g_Bt16 + (size_t)n0 * Ktot + k0;
        #pragma unroll
        for (int p = 0; p < 8; ++p) {
            int q = tid + 128 * p, row = q >> 3, c8 = (q & 7) * 8;
            cpa16(cvta_s(Bs + (row * ROWSTR + c8) * 2),
                  Bp + (size_t)row * Ktot + c8);
        }
        cpa_mbar_arrive(FULLB + s * 8);
    };

    load_stage(0, 0);
    load_stage(1, 1);

    uint32_t afr[2][4][4], bfr[2][4][4];
    int fph0 = 0, fph1 = 0, fph2 = 0;
    int eph0 = 0, eph1 = 0, eph2 = 0;

    // prologue: wait stage 0, preload its ks=0 fragments
    mbar_wait(FULLB + 0, 0); fph0 = 1;
    {
        const uint32_t sA = cvta_s(stg0);
        const uint32_t sB = sA + A_STG_B;
        #pragma unroll
        for (int mf = 0; mf < 4; ++mf)
            ldm4(afr[0][mf], sA + a_base + mf * (16 * ROWSTR * 2));
        #pragma unroll
        for (int np = 0; np < 4; ++np)
            ldm4(bfr[0][np], sB + b_base + np * (16 * ROWSTR * 2));
    }

    for (int it = 0; it < NITER; ++it) {
        const int s = it % NSTAGE;

        // producer: refill stage (it+2)%3 once its consumers drained
        if (it + 2 < NITER) {
            const int s2 = (it + 2) % NSTAGE;
            if (it > 0) {
                int ph = (s2 == 0) ? eph0 : (s2 == 1) ? eph1 : eph2;
                mbar_wait(EMPTB + s2 * 8, ph);
                if (s2 == 0) eph0 ^= 1; else if (s2 == 1) eph1 ^= 1; else eph2 ^= 1;
            }
            load_stage(s2, it + 2);
        }

        const uint32_t sA = cvta_s(stg0 + s * STG_B);
        const uint32_t sB = sA + A_STG_B;

        #pragma unroll
        for (int ks = 0; ks < 4; ++ks) {
            const int cur = ks & 1;
            const int nxt = cur ^ 1;
            if (ks < 3) {
                #pragma unroll
                for (int mf = 0; mf < 4; ++mf)
                    ldm4(afr[nxt][mf],
                         sA + a_base + mf * (16 * ROWSTR * 2) + (ks + 1) * 32);
                #pragma unroll
                for (int np = 0; np < 4; ++np)
                    ldm4(bfr[nxt][np],
                         sB + b_base + np * (16 * ROWSTR * 2) + (ks + 1) * 32);
                if (ks == 2)
                    mbar_arrive(EMPTB + s * 8);
            } else if (it + 1 < NITER) {
                const int s1 = (it + 1) % NSTAGE;
                int ph = (s1 == 0) ? fph0 : (s1 == 1) ? fph1 : fph2;
                mbar_wait(FULLB + s1 * 8, ph);
                if (s1 == 0) fph0 ^= 1; else if (s1 == 1) fph1 ^= 1; else fph2 ^= 1;
                const uint32_t nA = cvta_s(stg0 + s1 * STG_B);
                const uint32_t nB = nA + A_STG_B;
                #pragma unroll
                for (int mf = 0; mf < 4; ++mf)
                    ldm4(afr[nxt][mf], nA + a_base + mf * (16 * ROWSTR * 2));
                #pragma unroll
                for (int np = 0; np < 4; ++np)
                    ldm4(bfr[nxt][np], nB + b_base + np * (16 * ROWSTR * 2));
            }
            #pragma unroll
            for (int mf = 0; mf < 4; ++mf)
                #pragma unroll
                for (int np = 0; np < 4; ++np) {
                    mma16(acc[mf][np * 2 + 0], afr[cur][mf], &bfr[cur][np][0]);
                    mma16(acc[mf][np * 2 + 1], afr[cur][mf], &bfr[cur][np][2]);
                }
        }
    }

    // ---- fused LSTM epilogue (thread-local: all 4 gates per j) ----
    const size_t HC = (size_t)Bsz * Hd;
    #pragma unroll
    for (int mf = 0; mf < 4; ++mf) {
        #pragma unroll
        for (int e = 0; e < 2; ++e) {
            size_t row = (size_t)m0 + wm * 64 + mf * 16 + (lane >> 2) + e * 8;
            #pragma unroll
            for (int half = 0; half < 2; ++half) {
                int q  = 2 * (lane & 3) + half * 8;
                int bq = wn * 16 + q;
                int j  = jb + bq;
                float2 cold = *reinterpret_cast<const float2*>(c + row * 512 + j);
                float hv[2], cv[2];
                #pragma unroll
                for (int d = 0; d < 2; ++d) {
                    float gi = acc[mf][0 + half][e * 2 + d] + biasS[     bq + d];
                    float gf = acc[mf][2 + half][e * 2 + d] + biasS[32 + bq + d];
                    float gg = acc[mf][4 + half][e * 2 + d] + biasS[64 + bq + d];
                    float go = acc[mf][6 + half][e * 2 + d] + biasS[96 + bq + d];
                    float i_ = sigm_(gi), f_ = sigm_(gf);
                    float g_ = tanh_(gg), o_ = sigm_(go);
                    float co = d ? cold.y : cold.x;
                    float cn = f_ * co + i_ * g_;
                    cv[d] = cn;
                    hv[d] = o_ * tanh_(cn);
                }
                *reinterpret_cast<float2*>(out + row * 512 + j) =
                    make_float2(hv[0], hv[1]);
                *reinterpret_cast<float2*>(out + HC + row * 512 + j) =
                    make_float2(cv[0], cv[1]);
            }
        }
    }
}

extern "C" void kernel_launch(void* const* d_in, const int* in_sizes, int n_in,
                              void* d_out, int out_size) {
    const float* x  = (const float*)d_in[0];
    const float* h  = (const float*)d_in[1];
    const float* c  = (const float*)d_in[2];
    const float* Wx = (const float*)d_in[3];
    const float* Wh = (const float*)d_in[4];
    const float* bx = (const float*)d_in[5];
    const float* bh = (const float*)d_in[6];
    float* out = (float*)d_out;

    static bool attr_set = false;
    if (!attr_set) {
        cudaFuncSetAttribute(lstm_mma,
                             cudaFuncAttributeMaxDynamicSharedMemorySize,
                             SMEM_BYTES);
        attr_set = true;
    }

    prep_all<<<PREP_BLKS, 256>>>(x, h, Wx, Wh);
    lstm_mma<<<dim3(FH / BN, Bsz / BM), 128, SMEM_BYTES>>>(c, bx, bh, out);
}

// round 14
// speedup vs baseline: 1.0295x; 1.0178x over previous
#include <cuda_runtime.h>
#include <cuda_fp16.h>
#include <cstdint>

// LSTM cell: gates = [x|h] @ [Wx;Wh] + bx + bh, fused epilogue.
// B=16384, IN=H=512, K=1024, N=4H=2048.
// Round 14: lstm_mma mainloop restored EXACTLY to R11 (best measured).
// prep_all kept from R13 (MLP=8, 16B stores; validated). Epilogue writes
// use st.global.cs (evict-first) -- write-once output stops polluting L2.

static constexpr int Bsz  = 16384;
static constexpr int INF  = 512;
static constexpr int Hd   = 512;
static constexpr int FH   = 2048;
static constexpr int Ktot = 1024;

#define BM 128
#define BN 128
#define BK 64
#define NSTAGE 3
#define NITER (Ktot / BK)              // 16
#define ROWSTR 72                      // halves per SMEM row (144 B)
#define A_STG_B (BM * ROWSTR * 2)
#define B_STG_B (BN * ROWSTR * 2)
#define STG_B   (A_STG_B + B_STG_B)    // 36864 B
#define SMEM_BYTES (1024 + NSTAGE * STG_B)   // 111616

#define PREP_A_BLKS 2048
#define PREP_W_BLKS (32 * 64)
#define PREP_BLKS   (PREP_A_BLKS + PREP_W_BLKS)

__device__ __half g_A16[(size_t)Bsz * Ktot];
__device__ __half g_Bt16[(size_t)FH * Ktot];

// ---------------- helpers ----------------
__device__ __forceinline__ uint32_t cvta_s(const void* p) {
    return (uint32_t)__cvta_generic_to_shared(p);
}
__device__ __forceinline__ void cpa16(uint32_t s, const void* g) {
    asm volatile("cp.async.cg.shared.global [%0], [%1], 16;"
                 :: "r"(s), "l"(g) : "memory");
}
__device__ __forceinline__ void mbar_init(uint32_t a, uint32_t cnt) {
    asm volatile("mbarrier.init.shared.b64 [%0], %1;" :: "r"(a), "r"(cnt) : "memory");
}
__device__ __forceinline__ void mbar_arrive(uint32_t a) {
    asm volatile("mbarrier.arrive.shared.b64 _, [%0];" :: "r"(a) : "memory");
}
__device__ __forceinline__ void cpa_mbar_arrive(uint32_t a) {
    asm volatile("cp.async.mbarrier.arrive.noinc.shared.b64 [%0];"
                 :: "r"(a) : "memory");
}
__device__ __forceinline__ void mbar_wait(uint32_t a, uint32_t ph) {
    uint32_t done = 0;
    while (!done) {
        asm volatile(
            "{\n\t.reg .pred p;\n\t"
            "mbarrier.try_wait.parity.acquire.cta.shared::cta.b64 p, [%1], %2, 0x989680;\n\t"
            "selp.b32 %0, 1, 0, p;\n\t}"
            : "=r"(done) : "r"(a), "r"(ph) : "memory");
    }
}
__device__ __forceinline__ void ldm4(uint32_t* r, uint32_t a) {
    asm volatile("ldmatrix.sync.aligned.m8n8.x4.shared.b16 {%0,%1,%2,%3}, [%4];"
                 : "=r"(r[0]), "=r"(r[1]), "=r"(r[2]), "=r"(r[3]) : "r"(a));
}
__device__ __forceinline__ void mma16(float* d, const uint32_t* a, const uint32_t* b) {
    asm volatile(
        "mma.sync.aligned.m16n8k16.row.col.f32.f16.f16.f32 "
        "{%0,%1,%2,%3}, {%4,%5,%6,%7}, {%8,%9}, {%0,%1,%2,%3};"
        : "+f"(d[0]), "+f"(d[1]), "+f"(d[2]), "+f"(d[3])
        : "r"(a[0]), "r"(a[1]), "r"(a[2]), "r"(a[3]), "r"(b[0]), "r"(b[1]));
}
__device__ __forceinline__ float rcp_(float a) {
    float r; asm("rcp.approx.f32 %0, %1;" : "=f"(r) : "f"(a)); return r;
}
__device__ __forceinline__ float sigm_(float v) { return rcp_(1.0f + __expf(-v)); }
__device__ __forceinline__ float tanh_(float v) {
    return 2.0f * rcp_(1.0f + __expf(-2.0f * v)) - 1.0f;
}
__device__ __forceinline__ void stg_cs_v2(float* p, float a, float b) {
    asm volatile("st.global.cs.v2.f32 [%0], {%1, %2};"
                 :: "l"(p), "f"(a), "f"(b) : "memory");
}
__device__ __forceinline__ uint4 pack8h(const float4& a, const float4& b) {
    union { __half2 h2[4]; uint4 u; } u;
    u.h2[0] = __floats2half2_rn(a.x, a.y);
    u.h2[1] = __floats2half2_rn(a.z, a.w);
    u.h2[2] = __floats2half2_rn(b.x, b.y);
    u.h2[3] = __floats2half2_rn(b.z, b.w);
    return u.u;
}

// ---------------- merged prepass (R13, validated) ----------------
__global__ void prep_all(const float* __restrict__ x, const float* __restrict__ h,
                         const float* __restrict__ Wx, const float* __restrict__ Wh)
{
    if (blockIdx.x < PREP_A_BLKS) {
        const size_t t = (size_t)blockIdx.x * 256 + threadIdx.x;
        const size_t NG = (size_t)Bsz * INF / 8;
        const size_t S  = NG / 2;
        const size_t g0 = t, g1 = t + S;
        float4 x0a = *reinterpret_cast<const float4*>(x + g0 * 8);
        float4 x0b = *reinterpret_cast<const float4*>(x + g0 * 8 + 4);
        float4 x1a = *reinterpret_cast<const float4*>(x + g1 * 8);
        float4 x1b = *reinterpret_cast<const float4*>(x + g1 * 8 + 4);
        float4 h0a = *reinterpret_cast<const float4*>(h + g0 * 8);
        float4 h0b = *reinterpret_cast<const float4*>(h + g0 * 8 + 4);
        float4 h1a = *reinterpret_cast<const float4*>(h + g1 * 8);
        float4 h1b = *reinterpret_cast<const float4*>(h + g1 * 8 + 4);
        {   size_t b = g0 >> 6, c8 = (g0 & 63) * 8;
            *reinterpret_cast<uint4*>(g_A16 + b * Ktot + c8) = pack8h(x0a, x0b);
            *reinterpret_cast<uint4*>(g_A16 + b * Ktot + 512 + c8) = pack8h(h0a, h0b);
        }
        {   size_t b = g1 >> 6, c8 = (g1 & 63) * 8;
            *reinterpret_cast<uint4*>(g_A16 + b * Ktot + c8) = pack8h(x1a, x1b);
            *reinterpret_cast<uint4*>(g_A16 + b * Ktot + 512 + c8) = pack8h(h1a, h1b);
        }
        return;
    }

    __shared__ float t[32][33];
    const int wb = blockIdx.x - PREP_A_BLKS;
    const int k0 = (wb & 31) * 32;
    const int n0 = (wb >> 5) * 32;
    const float* W = (k0 < INF) ? (Wx + (size_t)k0 * FH)
                                : (Wh + (size_t)(k0 - INF) * FH);
    const int tx = threadIdx.x & 31, ty = threadIdx.x >> 5;
    #pragma unroll
    for (int i = 0; i < 4; ++i) {
        int kk = ty + i * 8;
        t[kk][tx] = W[(size_t)kk * FH + n0 + tx];
    }
    __syncthreads();
    const int gate = n0 >> 9;
    const int j0   = n0 & 511;
    #pragma unroll
    for (int i = 0; i < 4; ++i) {
        int nn = ty + i * 8;
        int j  = j0 + nn;
        int np = ((j >> 4) << 6) + gate * 16 + (j & 15);
        g_Bt16[(size_t)np * Ktot + k0 + tx] = __float2half_rn(t[tx][nn]);
    }
}

// ---------------- main GEMM + LSTM epilogue (R11 verbatim mainloop) --------
__global__ __launch_bounds__(128, 2)
void lstm_mma(const float* __restrict__ c,
              const float* __restrict__ bx, const float* __restrict__ bh,
              float* __restrict__ out)
{
    extern __shared__ char smraw[];
    float* biasS = reinterpret_cast<float*>(smraw);
    char*  stg0  = smraw + 1024;

    const int tid  = threadIdx.x;
    const int lane = tid & 31;
    const int wid  = tid >> 5;
    const int wm   = wid >> 1;
    const int wn   = wid & 1;
    const int m0   = blockIdx.y * BM;
    const int n0   = blockIdx.x * BN;
    const int jb   = blockIdx.x * 32;

    const uint32_t sbase = cvta_s(smraw);
    const uint32_t FULLB = sbase + 512;
    const uint32_t EMPTB = sbase + 512 + 24;

    if (tid == 0) {
        #pragma unroll
        for (int s = 0; s < NSTAGE; ++s) {
            mbar_init(FULLB + s * 8, 128);
            mbar_init(EMPTB + s * 8, 128);
        }
    }
    {   int g = tid >> 5, jj = tid & 31;
        int colg = g * 512 + jb + jj;
        biasS[tid] = bx[colg] + bh[colg];
    }
    __syncthreads();    // only CTA-wide barrier

    float acc[4][8][4];
    #pragma unroll
    for (int a = 0; a < 4; ++a)
        #pragma unroll
        for (int b = 0; b < 8; ++b)
            #pragma unroll
            for (int d = 0; d < 4; ++d) acc[a][b][d] = 0.0f;

    const int grp = lane >> 3, gi = lane & 7;
    const int a_row  = wm * 64 + (grp & 1) * 8 + gi;
    const int a_kofs = (grp >> 1) * 8;
    const uint32_t a_base = (uint32_t)(a_row * ROWSTR + a_kofs) * 2;
    const int b_row  = wn * 64 + (grp >> 1) * 8 + gi;
    const int b_kofs = (grp & 1) * 8;
    const uint32_t b_base = (uint32_t)(b_row * ROWSTR + b_kofs) * 2;

    auto load_stage = [&](int s, int kc) {
        const int k0 = kc * BK;
        char* As = stg0 + s * STG_B;
        char* Bs = As + A_STG_B;
        const __half* Ap = g_A16 + (size_t)m0 * Ktot + k0;
        #pragma unroll
        for (int p = 0; p < 8; ++p) {
            int q = tid + 128 * p, row = q >> 3, c8 = (q & 7) * 8;
            cpa16(cvta_s(As + (row * ROWSTR + c8) * 2),
                  Ap + (size_t)row * Ktot + c8);
        }
        const __half* Bp = g_Bt16 + (size_t)n0 * Ktot + k0;
        #pragma unroll
        for (int p = 0; p < 8; ++p) {
            int q = tid + 128 * p, row = q >> 3, c8 = (q & 7) * 8;
            cpa16(cvta_s(Bs + (row * ROWSTR + c8) * 2),
                  Bp + (size_t)row * Ktot + c8);
        }
        cpa_mbar_arrive(FULLB + s * 8);
    };

    load_stage(0, 0);
    load_stage(1, 1);

    uint32_t afr[2][4][4], bfr[2][4][4];
    int fph0 = 0, fph1 = 0, fph2 = 0;
    int eph0 = 0, eph1 = 0, eph2 = 0;

    // prologue: wait stage 0, preload its ks=0 fragments
    mbar_wait(FULLB + 0, 0); fph0 = 1;
    {
        const uint32_t sA = cvta_s(stg0);
        const uint32_t sB = sA + A_STG_B;
        #pragma unroll
        for (int mf = 0; mf < 4; ++mf)
            ldm4(afr[0][mf], sA + a_base + mf * (16 * ROWSTR * 2));
        #pragma unroll
        for (int np = 0; np < 4; ++np)
            ldm4(bfr[0][np], sB + b_base + np * (16 * ROWSTR * 2));
    }

    for (int it = 0; it < NITER; ++it) {
        const int s = it % NSTAGE;

        // producer: refill stage (it+2)%3 once its consumers drained
        if (it + 2 < NITER) {
            const int s2 = (it + 2) % NSTAGE;
            if (it > 0) {
                int ph = (s2 == 0) ? eph0 : (s2 == 1) ? eph1 : eph2;
                mbar_wait(EMPTB + s2 * 8, ph);
                if (s2 == 0) eph0 ^= 1; else if (s2 == 1) eph1 ^= 1; else eph2 ^= 1;
            }
            load_stage(s2, it + 2);
        }

        const uint32_t sA = cvta_s(stg0 + s * STG_B);
        const uint32_t sB = sA + A_STG_B;

        #pragma unroll
        for (int ks = 0; ks < 4; ++ks) {
            const int cur = ks & 1;
            const int nxt = cur ^ 1;
            if (ks < 3) {
                #pragma unroll
                for (int mf = 0; mf < 4; ++mf)
                    ldm4(afr[nxt][mf],
                         sA + a_base + mf * (16 * ROWSTR * 2) + (ks + 1) * 32);
                #pragma unroll
                for (int np = 0; np < 4; ++np)
                    ldm4(bfr[nxt][np],
                         sB + b_base + np * (16 * ROWSTR * 2) + (ks + 1) * 32);
                if (ks == 2)
                    mbar_arrive(EMPTB + s * 8);
            } else if (it + 1 < NITER) {
                const int s1 = (it + 1) % NSTAGE;
                int ph = (s1 == 0) ? fph0 : (s1 == 1) ? fph1 : fph2;
                mbar_wait(FULLB + s1 * 8, ph);
                if (s1 == 0) fph0 ^= 1; else if (s1 == 1) fph1 ^= 1; else fph2 ^= 1;
                const uint32_t nA = cvta_s(stg0 + s1 * STG_B);
                const uint32_t nB = nA + A_STG_B;
                #pragma unroll
                for (int mf = 0; mf < 4; ++mf)
                    ldm4(afr[nxt][mf], nA + a_base + mf * (16 * ROWSTR * 2));
                #pragma unroll
                for (int np = 0; np < 4; ++np)
                    ldm4(bfr[nxt][np], nB + b_base + np * (16 * ROWSTR * 2));
            }
            #pragma unroll
            for (int mf = 0; mf < 4; ++mf)
                #pragma unroll
                for (int np = 0; np < 4; ++np) {
                    mma16(acc[mf][np * 2 + 0], afr[cur][mf], &bfr[cur][np][0]);
                    mma16(acc[mf][np * 2 + 1], afr[cur][mf], &bfr[cur][np][2]);
                }
        }
    }

    // ---- fused LSTM epilogue (thread-local; streaming stores) ----
    const size_t HC = (size_t)Bsz * Hd;
    #pragma unroll
    for (int mf = 0; mf < 4; ++mf) {
        #pragma unroll
        for (int e = 0; e < 2; ++e) {
            size_t row = (size_t)m0 + wm * 64 + mf * 16 + (lane >> 2) + e * 8;
            #pragma unroll
            for (int half = 0; half < 2; ++half) {
                int q  = 2 * (lane & 3) + half * 8;
                int bq = wn * 16 + q;
                int j  = jb + bq;
                float2 cold = *reinterpret_cast<const float2*>(c + row * 512 + j);
                float hv[2], cv[2];
                #pragma unroll
                for (int d = 0; d < 2; ++d) {
                    float gi = acc[mf][0 + half][e * 2 + d] + biasS[     bq + d];
                    float gf = acc[mf][2 + half][e * 2 + d] + biasS[32 + bq + d];
                    float gg = acc[mf][4 + half][e * 2 + d] + biasS[64 + bq + d];
                    float go = acc[mf][6 + half][e * 2 + d] + biasS[96 + bq + d];
                    float i_ = sigm_(gi), f_ = sigm_(gf);
                    float g_ = tanh_(gg), o_ = sigm_(go);
                    float co = d ? cold.y : cold.x;
                    float cn = f_ * co + i_ * g_;
                    cv[d] = cn;
                    hv[d] = o_ * tanh_(cn);
                }
                stg_cs_v2(out + row * 512 + j, hv[0], hv[1]);
                stg_cs_v2(out + HC + row * 512 + j, cv[0], cv[1]);
            }
        }
    }
}

extern "C" void kernel_launch(void* const* d_in, const int* in_sizes, int n_in,
                              void* d_out, int out_size) {
    const float* x  = (const float*)d_in[0];
    const float* h  = (const float*)d_in[1];
    const float* c  = (const float*)d_in[2];
    const float* Wx = (const float*)d_in[3];
    const float* Wh = (const float*)d_in[4];
    const float* bx = (const float*)d_in[5];
    const float* bh = (const float*)d_in[6];
    float* out = (float*)d_out;

    static bool attr_set = false;
    if (!attr_set) {
        cudaFuncSetAttribute(lstm_mma,
                             cudaFuncAttributeMaxDynamicSharedMemorySize,
                             SMEM_BYTES);
        attr_set = true;
    }

    prep_all<<<PREP_BLKS, 256>>>(x, h, Wx, Wh);
    lstm_mma<<<dim3(FH / BN, Bsz / BM), 128, SMEM_BYTES>>>(c, bx, bh, out);
}

// round 15
// speedup vs baseline: 1.0433x; 1.0135x over previous
#include <cuda_runtime.h>
#include <cuda_fp16.h>
#include <cstdint>

// LSTM cell: gates = [x|h] @ [Wx;Wh] + bx + bh, fused epilogue.
// B=16384, IN=H=512, K=1024, N=4H=2048.
// Round 15: R11 mainloop VERBATIM (best measured; schedule-sensitive optimum)
// + R13 prep (MLP=8, 16B stores) + PDL overlap: prep triggers
// griddepcontrol.launch_dependents; main does its prep-independent prologue
// then griddepcontrol.wait right before the first cp.async stage.

static constexpr int Bsz  = 16384;
static constexpr int INF  = 512;
static constexpr int Hd   = 512;
static constexpr int FH   = 2048;
static constexpr int Ktot = 1024;

#define BM 128
#define BN 128
#define BK 64
#define NSTAGE 3
#define NITER (Ktot / BK)              // 16
#define ROWSTR 72                      // halves per SMEM row (144 B)
#define A_STG_B (BM * ROWSTR * 2)
#define B_STG_B (BN * ROWSTR * 2)
#define STG_B   (A_STG_B + B_STG_B)    // 36864 B
#define SMEM_BYTES (1024 + NSTAGE * STG_B)   // 111616

#define PREP_A_BLKS 2048
#define PREP_W_BLKS (32 * 64)
#define PREP_BLKS   (PREP_A_BLKS + PREP_W_BLKS)

__device__ __half g_A16[(size_t)Bsz * Ktot];
__device__ __half g_Bt16[(size_t)FH * Ktot];

// ---------------- helpers ----------------
__device__ __forceinline__ uint32_t cvta_s(const void* p) {
    return (uint32_t)__cvta_generic_to_shared(p);
}
__device__ __forceinline__ void cpa16(uint32_t s, const void* g) {
    asm volatile("cp.async.cg.shared.global [%0], [%1], 16;"
                 :: "r"(s), "l"(g) : "memory");
}
__device__ __forceinline__ void mbar_init(uint32_t a, uint32_t cnt) {
    asm volatile("mbarrier.init.shared.b64 [%0], %1;" :: "r"(a), "r"(cnt) : "memory");
}
__device__ __forceinline__ void mbar_arrive(uint32_t a) {
    asm volatile("mbarrier.arrive.shared.b64 _, [%0];" :: "r"(a) : "memory");
}
__device__ __forceinline__ void cpa_mbar_arrive(uint32_t a) {
    asm volatile("cp.async.mbarrier.arrive.noinc.shared.b64 [%0];"
                 :: "r"(a) : "memory");
}
__device__ __forceinline__ void mbar_wait(uint32_t a, uint32_t ph) {
    uint32_t done = 0;
    while (!done) {
        asm volatile(
            "{\n\t.reg .pred p;\n\t"
            "mbarrier.try_wait.parity.acquire.cta.shared::cta.b64 p, [%1], %2, 0x989680;\n\t"
            "selp.b32 %0, 1, 0, p;\n\t}"
            : "=r"(done) : "r"(a), "r"(ph) : "memory");
    }
}
__device__ __forceinline__ void ldm4(uint32_t* r, uint32_t a) {
    asm volatile("ldmatrix.sync.aligned.m8n8.x4.shared.b16 {%0,%1,%2,%3}, [%4];"
                 : "=r"(r[0]), "=r"(r[1]), "=r"(r[2]), "=r"(r[3]) : "r"(a));
}
__device__ __forceinline__ void mma16(float* d, const uint32_t* a, const uint32_t* b) {
    asm volatile(
        "mma.sync.aligned.m16n8k16.row.col.f32.f16.f16.f32 "
        "{%0,%1,%2,%3}, {%4,%5,%6,%7}, {%8,%9}, {%0,%1,%2,%3};"
        : "+f"(d[0]), "+f"(d[1]), "+f"(d[2]), "+f"(d[3])
        : "r"(a[0]), "r"(a[1]), "r"(a[2]), "r"(a[3]), "r"(b[0]), "r"(b[1]));
}
__device__ __forceinline__ float rcp_(float a) {
    float r; asm("rcp.approx.f32 %0, %1;" : "=f"(r) : "f"(a)); return r;
}
__device__ __forceinline__ float sigm_(float v) { return rcp_(1.0f + __expf(-v)); }
__device__ __forceinline__ float tanh_(float v) {
    return 2.0f * rcp_(1.0f + __expf(-2.0f * v)) - 1.0f;
}
__device__ __forceinline__ uint4 pack8h(const float4& a, const float4& b) {
    union { __half2 h2[4]; uint4 u; } u;
    u.h2[0] = __floats2half2_rn(a.x, a.y);
    u.h2[1] = __floats2half2_rn(a.z, a.w);
    u.h2[2] = __floats2half2_rn(b.x, b.y);
    u.h2[3] = __floats2half2_rn(b.z, b.w);
    return u.u;
}

// ---------------- merged prepass (R13, validated) ----------------
__global__ void prep_all(const float* __restrict__ x, const float* __restrict__ h,
                         const float* __restrict__ Wx, const float* __restrict__ Wh)
{
    // PDL: allow the dependent (main) grid to begin launching; fires once
    // all prep CTAs have executed this (i.e., during prep's last wave).
    asm volatile("griddepcontrol.launch_dependents;");

    if (blockIdx.x < PREP_A_BLKS) {
        const size_t t = (size_t)blockIdx.x * 256 + threadIdx.x;
        const size_t NG = (size_t)Bsz * INF / 8;
        const size_t S  = NG / 2;
        const size_t g0 = t, g1 = t + S;
        float4 x0a = *reinterpret_cast<const float4*>(x + g0 * 8);
        float4 x0b = *reinterpret_cast<const float4*>(x + g0 * 8 + 4);
        float4 x1a = *reinterpret_cast<const float4*>(x + g1 * 8);
        float4 x1b = *reinterpret_cast<const float4*>(x + g1 * 8 + 4);
        float4 h0a = *reinterpret_cast<const float4*>(h + g0 * 8);
        float4 h0b = *reinterpret_cast<const float4*>(h + g0 * 8 + 4);
        float4 h1a = *reinterpret_cast<const float4*>(h + g1 * 8);
        float4 h1b = *reinterpret_cast<const float4*>(h + g1 * 8 + 4);
        {   size_t b = g0 >> 6, c8 = (g0 & 63) * 8;
            *reinterpret_cast<uint4*>(g_A16 + b * Ktot + c8) = pack8h(x0a, x0b);
            *reinterpret_cast<uint4*>(g_A16 + b * Ktot + 512 + c8) = pack8h(h0a, h0b);
        }
        {   size_t b = g1 >> 6, c8 = (g1 & 63) * 8;
            *reinterpret_cast<uint4*>(g_A16 + b * Ktot + c8) = pack8h(x1a, x1b);
            *reinterpret_cast<uint4*>(g_A16 + b * Ktot + 512 + c8) = pack8h(h1a, h1b);
        }
        return;
    }

    __shared__ float t[32][33];
    const int wb = blockIdx.x - PREP_A_BLKS;
    const int k0 = (wb & 31) * 32;
    const int n0 = (wb >> 5) * 32;
    const float* W = (k0 < INF) ? (Wx + (size_t)k0 * FH)
                                : (Wh + (size_t)(k0 - INF) * FH);
    const int tx = threadIdx.x & 31, ty = threadIdx.x >> 5;
    #pragma unroll
    for (int i = 0; i < 4; ++i) {
        int kk = ty + i * 8;
        t[kk][tx] = W[(size_t)kk * FH + n0 + tx];
    }
    __syncthreads();
    const int gate = n0 >> 9;
    const int j0   = n0 & 511;
    #pragma unroll
    for (int i = 0; i < 4; ++i) {
        int nn = ty + i * 8;
        int j  = j0 + nn;
        int np = ((j >> 4) << 6) + gate * 16 + (j & 15);
        g_Bt16[(size_t)np * Ktot + k0 + tx] = __float2half_rn(t[tx][nn]);
    }
}

// ---------------- main GEMM + LSTM epilogue (R11 verbatim) ----------------
__global__ __launch_bounds__(128, 2)
void lstm_mma(const float* __restrict__ c,
              const float* __restrict__ bx, const float* __restrict__ bh,
              float* __restrict__ out)
{
    extern __shared__ char smraw[];
    float* biasS = reinterpret_cast<float*>(smraw);
    char*  stg0  = smraw + 1024;

    const int tid  = threadIdx.x;
    const int lane = tid & 31;
    const int wid  = tid >> 5;
    const int wm   = wid >> 1;
    const int wn   = wid & 1;
    const int m0   = blockIdx.y * BM;
    const int n0   = blockIdx.x * BN;
    const int jb   = blockIdx.x * 32;

    const uint32_t sbase = cvta_s(smraw);
    const uint32_t FULLB = sbase + 512;
    const uint32_t EMPTB = sbase + 512 + 24;

    if (tid == 0) {
        #pragma unroll
        for (int s = 0; s < NSTAGE; ++s) {
            mbar_init(FULLB + s * 8, 128);
            mbar_init(EMPTB + s * 8, 128);
        }
    }
    {   int g = tid >> 5, jj = tid & 31;
        int colg = g * 512 + jb + jj;
        biasS[tid] = bx[colg] + bh[colg];
    }
    __syncthreads();    // only CTA-wide barrier

    // PDL: block here until prep_all's stores are visible. Everything above
    // (mbarrier init, bias from bx/bh) is independent of prep output.
    asm volatile("griddepcontrol.wait;" ::: "memory");

    float acc[4][8][4];
    #pragma unroll
    for (int a = 0; a < 4; ++a)
        #pragma unroll
        for (int b = 0; b < 8; ++b)
            #pragma unroll
            for (int d = 0; d < 4; ++d) acc[a][b][d] = 0.0f;

    const int grp = lane >> 3, gi = lane & 7;
    const int a_row  = wm * 64 + (grp & 1) * 8 + gi;
    const int a_kofs = (grp >> 1) * 8;
    const uint32_t a_base = (uint32_t)(a_row * ROWSTR + a_kofs) * 2;
    const int b_row  = wn * 64 + (grp >> 1) * 8 + gi;
    const int b_kofs = (grp & 1) * 8;
    const uint32_t b_base = (uint32_t)(b_row * ROWSTR + b_kofs) * 2;

    auto load_stage = [&](int s, int kc) {
        const int k0 = kc * BK;
        char* As = stg0 + s * STG_B;
        char* Bs = As + A_STG_B;
        const __half* Ap = g_A16 + (size_t)m0 * Ktot + k0;
        #pragma unroll
        for (int p = 0; p < 8; ++p) {
            int q = tid + 128 * p, row = q >> 3, c8 = (q & 7) * 8;
            cpa16(cvta_s(As + (row * ROWSTR + c8) * 2),
                  Ap + (size_t)row * Ktot + c8);
        }
        const __half* Bp = g_Bt16 + (size_t)n0 * Ktot + k0;
        #pragma unroll
        for (int p = 0; p < 8; ++p) {
            int q = tid + 128 * p, row = q >> 3, c8 = (q & 7) * 8;
            cpa16(cvta_s(Bs + (row * ROWSTR + c8) * 2),
                  Bp + (size_t)row * Ktot + c8);
        }
        cpa_mbar_arrive(FULLB + s * 8);
    };

    load_stage(0, 0);
    load_stage(1, 1);

    uint32_t afr[2][4][4], bfr[2][4][4];
    int fph0 = 0, fph1 = 0, fph2 = 0;
    int eph0 = 0, eph1 = 0, eph2 = 0;

    // prologue: wait stage 0, preload its ks=0 fragments
    mbar_wait(FULLB + 0, 0); fph0 = 1;
    {
        const uint32_t sA = cvta_s(stg0);
        const uint32_t sB = sA + A_STG_B;
        #pragma unroll
        for (int mf = 0; mf < 4; ++mf)
            ldm4(afr[0][mf], sA + a_base + mf * (16 * ROWSTR * 2));
        #pragma unroll
        for (int np = 0; np < 4; ++np)
            ldm4(bfr[0][np], sB + b_base + np * (16 * ROWSTR * 2));
    }

    for (int it = 0; it < NITER; ++it) {
        const int s = it % NSTAGE;

        // producer: refill stage (it+2)%3 once its consumers drained
        if (it + 2 < NITER) {
            const int s2 = (it + 2) % NSTAGE;
            if (it > 0) {
                int ph = (s2 == 0) ? eph0 : (s2 == 1) ? eph1 : eph2;
                mbar_wait(EMPTB + s2 * 8, ph);
                if (s2 == 0) eph0 ^= 1; else if (s2 == 1) eph1 ^= 1; else eph2 ^= 1;
            }
            load_stage(s2, it + 2);
        }

        const uint32_t sA = cvta_s(stg0 + s * STG_B);
        const uint32_t sB = sA + A_STG_B;

        #pragma unroll
        for (int ks = 0; ks < 4; ++ks) {
            const int cur = ks & 1;
            const int nxt = cur ^ 1;
            if (ks < 3) {
                #pragma unroll
                for (int mf = 0; mf < 4; ++mf)
                    ldm4(afr[nxt][mf],
                         sA + a_base + mf * (16 * ROWSTR * 2) + (ks + 1) * 32);
                #pragma unroll
                for (int np = 0; np < 4; ++np)
                    ldm4(bfr[nxt][np],
                         sB + b_base + np * (16 * ROWSTR * 2) + (ks + 1) * 32);
                if (ks == 2)
                    mbar_arrive(EMPTB + s * 8);
            } else if (it + 1 < NITER) {
                const int s1 = (it + 1) % NSTAGE;
                int ph = (s1 == 0) ? fph0 : (s1 == 1) ? fph1 : fph2;
                mbar_wait(FULLB + s1 * 8, ph);
                if (s1 == 0) fph0 ^= 1; else if (s1 == 1) fph1 ^= 1; else fph2 ^= 1;
                const uint32_t nA = cvta_s(stg0 + s1 * STG_B);
                const uint32_t nB = nA + A_STG_B;
                #pragma unroll
                for (int mf = 0; mf < 4; ++mf)
                    ldm4(afr[nxt][mf], nA + a_base + mf * (16 * ROWSTR * 2));
                #pragma unroll
                for (int np = 0; np < 4; ++np)
                    ldm4(bfr[nxt][np], nB + b_base + np * (16 * ROWSTR * 2));
            }
            #pragma unroll
            for (int mf = 0; mf < 4; ++mf)
                #pragma unroll
                for (int np = 0; np < 4; ++np) {
                    mma16(acc[mf][np * 2 + 0], afr[cur][mf], &bfr[cur][np][0]);
                    mma16(acc[mf][np * 2 + 1], afr[cur][mf], &bfr[cur][np][2]);
                }
        }
    }

    // ---- fused LSTM epilogue (thread-local: all 4 gates per j) ----
    const size_t HC = (size_t)Bsz * Hd;
    #pragma unroll
    for (int mf = 0; mf < 4; ++mf) {
        #pragma unroll
        for (int e = 0; e < 2; ++e) {
            size_t row = (size_t)m0 + wm * 64 + mf * 16 + (lane >> 2) + e * 8;
            #pragma unroll
            for (int half = 0; half < 2; ++half) {
                int q  = 2 * (lane & 3) + half * 8;
                int bq = wn * 16 + q;
                int j  = jb + bq;
                float2 cold = *reinterpret_cast<const float2*>(c + row * 512 + j);
                float hv[2], cv[2];
                #pragma unroll
                for (int d = 0; d < 2; ++d) {
                    float gi = acc[mf][0 + half][e * 2 + d] + biasS[     bq + d];
                    float gf = acc[mf][2 + half][e * 2 + d] + biasS[32 + bq + d];
                    float gg = acc[mf][4 + half][e * 2 + d] + biasS[64 + bq + d];
                    float go = acc[mf][6 + half][e * 2 + d] + biasS[96 + bq + d];
                    float i_ = sigm_(gi), f_ = sigm_(gf);
                    float g_ = tanh_(gg), o_ = sigm_(go);
                    float co = d ? cold.y : cold.x;
                    float cn = f_ * co + i_ * g_;
                    cv[d] = cn;
                    hv[d] = o_ * tanh_(cn);
                }
                *reinterpret_cast<float2*>(out + row * 512 + j) =
                    make_float2(hv[0], hv[1]);
                *reinterpret_cast<float2*>(out + HC + row * 512 + j) =
                    make_float2(cv[0], cv[1]);
            }
        }
    }
}

extern "C" void kernel_launch(void* const* d_in, const int* in_sizes, int n_in,
                              void* d_out, int out_size) {
    const float* x  = (const float*)d_in[0];
    const float* h  = (const float*)d_in[1];
    const float* c  = (const float*)d_in[2];
    const float* Wx = (const float*)d_in[3];
    const float* Wh = (const float*)d_in[4];
    const float* bx = (const float*)d_in[5];
    const float* bh = (const float*)d_in[6];
    float* out = (float*)d_out;

    static bool attr_set = false;
    if (!attr_set) {
        cudaFuncSetAttribute(lstm_mma,
                             cudaFuncAttributeMaxDynamicSharedMemorySize,
                             SMEM_BYTES);
        attr_set = true;
    }

    prep_all<<<PREP_BLKS, 256>>>(x, h, Wx, Wh);

    // PDL launch of the dependent main kernel
    cudaLaunchConfig_t cfg = {};
    cfg.gridDim  = dim3(FH / BN, Bsz / BM);
    cfg.blockDim = dim3(128);
    cfg.dynamicSmemBytes = SMEM_BYTES;
    cfg.stream = 0;
    cudaLaunchAttribute attrs[1];
    attrs[0].id = cudaLaunchAttributeProgrammaticStreamSerialization;
    attrs[0].val.programmaticStreamSerializationAllowed = 1;
    cfg.attrs = attrs;
    cfg.numAttrs = 1;
    cudaLaunchKernelEx(&cfg, lstm_mma, c, bx, bh, out);
}